// round 1
// baseline (speedup 1.0000x reference)
#include <cuda_runtime.h>
#include <math.h>

// ----------------------------------------------------------------------------
// UnifiedKAN: 2-layer KAN with learned-knot cubic B-splines.
// Strategy: splines are piecewise cubics over 6 real intervals. A tiny setup
// kernel fits exact per-interval cubics (centered monomial form, fitted in
// double from float32-reference samples), then the main kernel evaluates
// 20 cubics per sample via interval search + Horner.
// ----------------------------------------------------------------------------

#define GRID_ 5
#define DEG_ 3
#define NC_ 8          // GRID + DEG
#define IN_ 4
#define HID_ 4
#define NSPL 20        // 16 layer-1 edges + 4 layer-2 units
#define SPL_STRIDE 40  // floats per spline: [0..4] interior knots, [5..10] centers, [11..15] pad, [16+4j..] c0..c3
#define PARAMS_W 800   // offset of softmax weights (8 floats)
#define PARAMS_B 808   // offset of base scalar
#define PARAMS_N 809

__device__ float g_params[832];

// Exact replica of the reference float32 Cox-de Boor recursion (with truncation
// to the first NC_=8 basis functions and the x==knots[-1] endpoint fix).
__device__ float eval_ref_spline(float x, const float* kn /*13*/, const float* cf /*8*/) {
    float b[12];
    #pragma unroll
    for (int j = 0; j < 12; j++)
        b[j] = (x >= kn[j] && x < kn[j + 1]) ? 1.0f : 0.0f;
    if (x == kn[12]) b[11] += 1.0f;
    for (int d = 1; d <= 3; d++) {
        int n = 12 - d;
        for (int j = 0; j < n; j++) {
            float den1 = kn[d + j] - kn[j];
            float den2 = kn[d + 1 + j] - kn[1 + j];
            float t1 = (den1 > 1e-8f) ? (x - kn[j]) / den1 * b[j] : 0.0f;
            float t2 = (den2 > 1e-8f) ? (kn[d + 1 + j] - x) / den2 * b[j + 1] : 0.0f;
            b[j] = t1 + t2;  // in-place ascending: b[j+1] still old value
        }
    }
    float s = 0.0f;
    #pragma unroll
    for (int j = 0; j < NC_; j++) s += b[j] * cf[j];
    return s;
}

__global__ void kan_setup_kernel(const float* __restrict__ l1_coeffs,
                                 const float* __restrict__ l1_kd,
                                 const float* __restrict__ op_alpha,
                                 const float* __restrict__ gumbel,
                                 const float* __restrict__ l2_coeffs,
                                 const float* __restrict__ l2_kd,
                                 const float* __restrict__ base_offset) {
    int s = threadIdx.x;
    if (s < NSPL) {
        const float* kd = (s < 16) ? (l1_kd + s * (GRID_ + 1)) : (l2_kd + (s - 16) * (GRID_ + 1));
        const float* cf = (s < 16) ? (l1_coeffs + s * NC_) : (l2_coeffs + (s - 16) * NC_);

        // knots: softplus -> normalize to total 2 -> cumsum from -1, clamp pad DEG_
        float d[GRID_ + 1];
        float dsum = 0.0f;
        #pragma unroll
        for (int k = 0; k < GRID_ + 1; k++) {
            float v = kd[k];
            d[k] = fmaxf(v, 0.0f) + log1pf(expf(-fabsf(v)));  // stable softplus (jax logaddexp(x,0))
            dsum += d[k];
        }
        float kn[13];
        kn[0] = kn[1] = kn[2] = kn[3] = -1.0f;
        float cum = 0.0f;
        #pragma unroll
        for (int k = 0; k < 5; k++) {             // interior[:-1] -> 5 interior knots
            float dn = d[k] / dsum * 2.0f;
            cum += dn;
            kn[4 + k] = -1.0f + cum;
        }
        kn[9] = kn[10] = kn[11] = kn[12] = 1.0f;

        float* P = g_params + s * SPL_STRIDE;
        #pragma unroll
        for (int k = 0; k < 5; k++) P[k] = kn[4 + k];

        // Fit exact cubic on each of the 6 real intervals [kn[3+j], kn[4+j]].
        for (int j = 0; j < 6; j++) {
            float lo = kn[3 + j], hi = kn[4 + j];
            double m = 0.5 * ((double)lo + (double)hi);
            float u[4];
            double fv[4], v[4];
            #pragma unroll
            for (int k = 0; k < 4; k++) {
                u[k] = lo + (hi - lo) * (0.125f + 0.25f * (float)k);
                fv[k] = (double)eval_ref_spline(u[k], kn, cf);
                v[k] = (double)u[k] - m;
            }
            // Newton divided differences (double)
            double c0    = fv[0];
            double c01   = (fv[1] - fv[0]) / (v[1] - v[0]);
            double c12   = (fv[2] - fv[1]) / (v[2] - v[1]);
            double c23   = (fv[3] - fv[2]) / (v[3] - v[2]);
            double c012  = (c12 - c01) / (v[2] - v[0]);
            double c123  = (c23 - c12) / (v[3] - v[1]);
            double c0123 = (c123 - c012) / (v[3] - v[0]);
            // Expand Newton form to monomial in t = x - m:
            // p = ((c0123*(t-v2)+c012)*(t-v1)+c01)*(t-v0)+c0
            double p0 = c0123, p1 = 0.0, p2 = 0.0, p3 = 0.0;
            double nodes[3] = {v[2], v[1], v[0]};
            double adds[3]  = {c012, c01, c0};
            #pragma unroll
            for (int st = 0; st < 3; st++) {
                double q3 = p2, q2 = p1, q1 = p0, q0 = 0.0;  // p * t
                double vv = nodes[st];
                q0 -= vv * p0; q1 -= vv * p1; q2 -= vv * p2; q3 -= vv * p3;
                q0 += adds[st];
                p0 = q0; p1 = q1; p2 = q2; p3 = q3;
            }
            P[5 + j] = (float)m;
            P[16 + 4 * j + 0] = (float)p0;
            P[16 + 4 * j + 1] = (float)p1;
            P[16 + 4 * j + 2] = (float)p2;
            P[16 + 4 * j + 3] = (float)p3;
        }
    }
    if (s == NSPL) {
        #pragma unroll
        for (int h = 0; h < HID_; h++) {
            float a0 = op_alpha[h * 2 + 0] + gumbel[h * 2 + 0];
            float a1 = op_alpha[h * 2 + 1] + gumbel[h * 2 + 1];
            float mx = fmaxf(a0, a1);
            float e0 = expf(a0 - mx), e1 = expf(a1 - mx);
            float inv = 1.0f / (e0 + e1);
            g_params[PARAMS_W + h * 2 + 0] = e0 * inv;
            g_params[PARAMS_W + h * 2 + 1] = e1 * inv;
        }
        g_params[PARAMS_B] = base_offset[0];
    }
}

__device__ __forceinline__ float eval_spline_sh(float x, const float* sp) {
    int idx = (x >= sp[0]) + (x >= sp[1]) + (x >= sp[2]) + (x >= sp[3]) + (x >= sp[4]);
    float m = sp[5 + idx];
    float4 c = *reinterpret_cast<const float4*>(sp + 16 + 4 * idx);
    float t = x - m;
    return fmaf(fmaf(fmaf(c.w, t, c.z), t, c.y), t, c.x);
}

__global__ void __launch_bounds__(256) kan_main_kernel(const float4* __restrict__ x,
                                                       float* __restrict__ out, int n) {
    __shared__ __align__(16) float sp[832];
    for (int k = threadIdx.x; k < PARAMS_N; k += blockDim.x) sp[k] = g_params[k];
    __syncthreads();

    int i0 = blockIdx.x * blockDim.x + threadIdx.x;
    if (i0 >= n) return;

    float4 xv = x[i0];
    float xi[4] = {xv.x, xv.y, xv.z, xv.w};

    float acc = sp[PARAMS_B];
    #pragma unroll
    for (int h = 0; h < HID_; h++) {
        float sum = 0.0f, prod = 1.0f;
        #pragma unroll
        for (int i = 0; i < IN_; i++) {
            float v = eval_spline_sh(xi[i], sp + (h * IN_ + i) * SPL_STRIDE);
            sum += v;
            float c = fminf(fmaxf(v, -5.0f), 5.0f);
            prod *= c;
        }
        float hid = sp[PARAMS_W + h * 2 + 0] * sum + sp[PARAMS_W + h * 2 + 1] * prod;
        float v2 = 0.0f;
        if (hid >= -1.0f && hid <= 1.0f)
            v2 = eval_spline_sh(hid, sp + (16 + h) * SPL_STRIDE);
        acc += v2;
    }
    out[i0] = acc;
}

extern "C" void kernel_launch(void* const* d_in, const int* in_sizes, int n_in,
                              void* d_out, int out_size) {
    const float* x          = (const float*)d_in[0];
    const float* l1_coeffs  = (const float*)d_in[1];
    const float* l1_kd      = (const float*)d_in[2];
    const float* op_alpha   = (const float*)d_in[3];
    const float* gumbel     = (const float*)d_in[4];
    const float* l2_coeffs  = (const float*)d_in[5];
    const float* l2_kd      = (const float*)d_in[6];
    const float* base_off   = (const float*)d_in[7];
    float* out = (float*)d_out;

    int n = in_sizes[0] / IN_;  // N samples

    kan_setup_kernel<<<1, 32>>>(l1_coeffs, l1_kd, op_alpha, gumbel,
                                l2_coeffs, l2_kd, base_off);
    int threads = 256;
    int blocks = (n + threads - 1) / threads;
    kan_main_kernel<<<blocks, threads>>>((const float4*)x, out, n);
}

// round 2
// speedup vs baseline: 6.3842x; 6.3842x over previous
#include <cuda_runtime.h>
#include <math.h>

// ----------------------------------------------------------------------------
// UnifiedKAN: 2-layer KAN with learned-knot cubic B-splines.
// Splines are piecewise cubics over 6 real intervals. Setup kernel (20 blocks,
// one per spline; lane-parallel node sampling + fp64 divided-difference fit)
// produces centered-monomial cubics; main kernel does interval search + Horner.
// ----------------------------------------------------------------------------

#define GRID_ 5
#define DEG_ 3
#define NC_ 8          // GRID + DEG
#define IN_ 4
#define HID_ 4
#define NSPL 20        // 16 layer-1 edges + 4 layer-2 units
#define SPL_STRIDE 40  // floats/spline: [0..4] interior knots, [5..10] centers, [16+4j..] c0..c3
#define PARAMS_W 800   // softmax weights (8 floats)
#define PARAMS_B 808   // base offset scalar
#define PARAMS_N 809

__device__ float g_params[832];

// Reference float32 Cox-de Boor recursion (truncated to first NC_=8 basis fns),
// with denominators replaced by precomputed reciprocals rc[] (0 when den<=1e-8).
// rc layout: d=1 -> rc[0..11], d=2 -> rc[12..22], d=3 -> rc[23..32].
__device__ __forceinline__ float eval_ref_spline(float x, const float* kn /*13*/,
                                                 const float* rc /*33*/,
                                                 const float* cf /*8*/) {
    float b[12];
    #pragma unroll
    for (int j = 0; j < 12; j++)
        b[j] = (x >= kn[j] && x < kn[j + 1]) ? 1.0f : 0.0f;
    if (x == kn[12]) b[11] += 1.0f;
    const int off[4] = {0, 0, 12, 23};
    #pragma unroll
    for (int d = 1; d <= 3; d++) {
        int n = 12 - d;
        const float* r = rc + off[d];
        #pragma unroll
        for (int j = 0; j < 11; j++) {
            if (j >= n) break;
            float t1 = (x - kn[j]) * r[j] * b[j];
            float t2 = (kn[d + 1 + j] - x) * r[j + 1] * b[j + 1];
            b[j] = t1 + t2;  // in-place ascending: b[j+1] still old value
        }
    }
    float s = 0.0f;
    #pragma unroll
    for (int j = 0; j < NC_; j++) s += b[j] * cf[j];
    return s;
}

// One block per spline, 32 threads (single warp).
__global__ void kan_setup_kernel(const float* __restrict__ l1_coeffs,
                                 const float* __restrict__ l1_kd,
                                 const float* __restrict__ op_alpha,
                                 const float* __restrict__ gumbel,
                                 const float* __restrict__ l2_coeffs,
                                 const float* __restrict__ l2_kd,
                                 const float* __restrict__ base_offset) {
    __shared__ float s_rc[33];
    __shared__ float s_fv[24];   // [6 intervals][4 nodes]

    int s = blockIdx.x;
    int lane = threadIdx.x;
    const float* kd = (s < 16) ? (l1_kd + s * (GRID_ + 1)) : (l2_kd + (s - 16) * (GRID_ + 1));
    const float* cf = (s < 16) ? (l1_coeffs + s * NC_) : (l2_coeffs + (s - 16) * NC_);

    // Every lane redundantly computes the 13-knot vector (cheap).
    float d[GRID_ + 1];
    float dsum = 0.0f;
    #pragma unroll
    for (int k = 0; k < GRID_ + 1; k++) {
        float v = kd[k];
        d[k] = fmaxf(v, 0.0f) + log1pf(expf(-fabsf(v)));  // stable softplus
        dsum += d[k];
    }
    float kn[13];
    kn[0] = kn[1] = kn[2] = kn[3] = -1.0f;
    float cum = 0.0f;
    #pragma unroll
    for (int k = 0; k < 5; k++) {
        cum += d[k] / dsum * 2.0f;
        kn[4 + k] = -1.0f + cum;
    }
    kn[9] = kn[10] = kn[11] = kn[12] = 1.0f;

    // Phase 0: reciprocals of the 33 distinct knot-difference denominators.
    for (int t = lane; t < 33; t += 32) {
        int dd, j;
        if (t < 12)      { dd = 1; j = t; }
        else if (t < 23) { dd = 2; j = t - 12; }
        else             { dd = 3; j = t - 23; }
        float den = kn[dd + j] - kn[j];
        s_rc[t] = (den > 1e-8f) ? 1.0f / den : 0.0f;
    }
    __syncthreads();

    // Phase 1: lanes 0..23 each sample ONE node of ONE interval.
    if (lane < 24) {
        int j = lane >> 2, k = lane & 3;
        float lo = kn[3 + j], hi = kn[4 + j];
        float u = lo + (hi - lo) * (0.125f + 0.25f * (float)k);
        s_fv[lane] = eval_ref_spline(u, kn, s_rc, cf);
    } else if (s == 0) {
        int h = lane - 24;
        if (h < HID_) {
            float a0 = op_alpha[h * 2 + 0] + gumbel[h * 2 + 0];
            float a1 = op_alpha[h * 2 + 1] + gumbel[h * 2 + 1];
            float mx = fmaxf(a0, a1);
            float e0 = expf(a0 - mx), e1 = expf(a1 - mx);
            float inv = 1.0f / (e0 + e1);
            g_params[PARAMS_W + h * 2 + 0] = e0 * inv;
            g_params[PARAMS_W + h * 2 + 1] = e1 * inv;
        }
        if (lane == 28) g_params[PARAMS_B] = base_offset[0];
    }
    __syncthreads();

    float* P = g_params + s * SPL_STRIDE;
    if (lane < 5) P[lane] = kn[4 + lane];  // interior knots

    // Phase 2: lanes 0..5 fit the exact cubic for interval j (fp64 Newton).
    if (lane < 6) {
        int j = lane;
        float lo = kn[3 + j], hi = kn[4 + j];
        double m = 0.5 * ((double)lo + (double)hi);
        double fv[4], v[4];
        #pragma unroll
        for (int k = 0; k < 4; k++) {
            float u = lo + (hi - lo) * (0.125f + 0.25f * (float)k);
            fv[k] = (double)s_fv[j * 4 + k];
            v[k] = (double)u - m;
        }
        double c0    = fv[0];
        double c01   = (fv[1] - fv[0]) / (v[1] - v[0]);
        double c12   = (fv[2] - fv[1]) / (v[2] - v[1]);
        double c23   = (fv[3] - fv[2]) / (v[3] - v[2]);
        double c012  = (c12 - c01) / (v[2] - v[0]);
        double c123  = (c23 - c12) / (v[3] - v[1]);
        double c0123 = (c123 - c012) / (v[3] - v[0]);
        // Expand Newton form to monomial in t = x - m.
        double p0 = c0123, p1 = 0.0, p2 = 0.0, p3 = 0.0;
        double nodes[3] = {v[2], v[1], v[0]};
        double adds[3]  = {c012, c01, c0};
        #pragma unroll
        for (int st = 0; st < 3; st++) {
            double vv = nodes[st];
            double q3 = p2, q2 = p1, q1 = p0;
            double q0 = adds[st] - vv * p0;
            q1 -= vv * p1; q2 -= vv * p2; q3 -= vv * p3;
            p0 = q0; p1 = q1; p2 = q2; p3 = q3;
        }
        P[5 + j] = (float)m;
        P[16 + 4 * j + 0] = (float)p0;
        P[16 + 4 * j + 1] = (float)p1;
        P[16 + 4 * j + 2] = (float)p2;
        P[16 + 4 * j + 3] = (float)p3;
    }
}

__device__ __forceinline__ float eval_spline_sh(float x, const float* sp) {
    int idx = (x >= sp[0]) + (x >= sp[1]) + (x >= sp[2]) + (x >= sp[3]) + (x >= sp[4]);
    float m = sp[5 + idx];
    float4 c = *reinterpret_cast<const float4*>(sp + 16 + 4 * idx);
    float t = x - m;
    return fmaf(fmaf(fmaf(c.w, t, c.z), t, c.y), t, c.x);
}

__device__ __forceinline__ float kan_sample(float4 xv, const float* sp) {
    float xi[4] = {xv.x, xv.y, xv.z, xv.w};
    float acc = sp[PARAMS_B];
    #pragma unroll
    for (int h = 0; h < HID_; h++) {
        float sum = 0.0f, prod = 1.0f;
        #pragma unroll
        for (int i = 0; i < IN_; i++) {
            float v = eval_spline_sh(xi[i], sp + (h * IN_ + i) * SPL_STRIDE);
            sum += v;
            prod *= fminf(fmaxf(v, -5.0f), 5.0f);
        }
        float hid = sp[PARAMS_W + h * 2 + 0] * sum + sp[PARAMS_W + h * 2 + 1] * prod;
        if (hid >= -1.0f && hid <= 1.0f)
            acc += eval_spline_sh(hid, sp + (16 + h) * SPL_STRIDE);
    }
    return acc;
}

__global__ void __launch_bounds__(256) kan_main_kernel(const float4* __restrict__ x,
                                                       float* __restrict__ out, int n) {
    __shared__ __align__(16) float sp[832];
    for (int k = threadIdx.x; k < PARAMS_N; k += blockDim.x) sp[k] = g_params[k];
    __syncthreads();

    int i0 = blockIdx.x * (blockDim.x * 2) + threadIdx.x;
    int i1 = i0 + blockDim.x;

    if (i1 < n) {
        float4 xa = x[i0];
        float4 xb = x[i1];
        float ra = kan_sample(xa, sp);
        float rb = kan_sample(xb, sp);
        out[i0] = ra;
        out[i1] = rb;
    } else if (i0 < n) {
        out[i0] = kan_sample(x[i0], sp);
    }
}

extern "C" void kernel_launch(void* const* d_in, const int* in_sizes, int n_in,
                              void* d_out, int out_size) {
    const float* x          = (const float*)d_in[0];
    const float* l1_coeffs  = (const float*)d_in[1];
    const float* l1_kd      = (const float*)d_in[2];
    const float* op_alpha   = (const float*)d_in[3];
    const float* gumbel     = (const float*)d_in[4];
    const float* l2_coeffs  = (const float*)d_in[5];
    const float* l2_kd      = (const float*)d_in[6];
    const float* base_off   = (const float*)d_in[7];
    float* out = (float*)d_out;

    int n = in_sizes[0] / IN_;  // N samples

    kan_setup_kernel<<<NSPL, 32>>>(l1_coeffs, l1_kd, op_alpha, gumbel,
                                   l2_coeffs, l2_kd, base_off);
    int threads = 256;
    int blocks = (n + threads * 2 - 1) / (threads * 2);
    kan_main_kernel<<<blocks, threads>>>((const float4*)x, out, n);
}

// round 3
// speedup vs baseline: 7.5686x; 1.1855x over previous
#include <cuda_runtime.h>
#include <math.h>

// ----------------------------------------------------------------------------
// UnifiedKAN: 2-layer KAN with learned-knot cubic B-splines.
// Splines = piecewise cubics over 6 real intervals. Setup (20 blocks, fp32,
// one reciprocal per interval fit) -> centered-monomial cubics. Main kernel:
// vectorized interval search (1x LDS.128 + 1 scalar) + Horner.
// ----------------------------------------------------------------------------

#define GRID_ 5
#define IN_ 4
#define HID_ 4
#define NSPL 20
// Per-spline record (40 floats, 160B, 16B-aligned):
// [0..3] interior knots 0..3 (float4), [4] knot 4, [5..7] pad,
// [8..13] interval centers m[0..5], [14..15] pad, [16+4j..] coefs c0..c3.
#define SPL_STRIDE 40
#define PARAMS_W 800   // softmax weights (8 floats)
#define PARAMS_B 808   // base offset scalar
#define PARAMS_N 809

__device__ float g_params[832];

// Reference float32 Cox-de Boor (truncated to first 8 basis fns), denominators
// replaced by precomputed reciprocals rc[] (0 when den<=1e-8).
// rc layout: d=1 -> rc[0..11], d=2 -> rc[12..22], d=3 -> rc[23..32].
__device__ __forceinline__ float eval_ref_spline(float x, const float* kn /*13*/,
                                                 const float* rc /*33*/,
                                                 const float* cf /*8*/) {
    float b[12];
    #pragma unroll
    for (int j = 0; j < 12; j++)
        b[j] = (x >= kn[j] && x < kn[j + 1]) ? 1.0f : 0.0f;
    if (x == kn[12]) b[11] += 1.0f;
    const int off[4] = {0, 0, 12, 23};
    #pragma unroll
    for (int d = 1; d <= 3; d++) {
        int n = 12 - d;
        const float* r = rc + off[d];
        #pragma unroll
        for (int j = 0; j < 11; j++) {
            if (j >= n) break;
            float t1 = (x - kn[j]) * r[j] * b[j];
            float t2 = (kn[d + 1 + j] - x) * r[j + 1] * b[j + 1];
            b[j] = t1 + t2;  // in-place ascending: b[j+1] still old value
        }
    }
    float s = 0.0f;
    #pragma unroll
    for (int j = 0; j < 8; j++) s += b[j] * cf[j];
    return s;
}

// One block per spline, 32 threads.
__global__ void kan_setup_kernel(const float* __restrict__ l1_coeffs,
                                 const float* __restrict__ l1_kd,
                                 const float* __restrict__ op_alpha,
                                 const float* __restrict__ gumbel,
                                 const float* __restrict__ l2_coeffs,
                                 const float* __restrict__ l2_kd,
                                 const float* __restrict__ base_offset) {
    __shared__ float s_rc[33];
    __shared__ float s_fv[24];   // [6 intervals][4 nodes]

    int s = blockIdx.x;
    int lane = threadIdx.x;
    const float* kd = (s < 16) ? (l1_kd + s * (GRID_ + 1)) : (l2_kd + (s - 16) * (GRID_ + 1));
    const float* cf = (s < 16) ? (l1_coeffs + s * 8) : (l2_coeffs + (s - 16) * 8);

    // Every lane redundantly computes the 13-knot vector (cheap, lockstep).
    float d[GRID_ + 1];
    float dsum = 0.0f;
    #pragma unroll
    for (int k = 0; k < GRID_ + 1; k++) {
        float v = kd[k];
        d[k] = fmaxf(v, 0.0f) + log1pf(expf(-fabsf(v)));  // stable softplus
        dsum += d[k];
    }
    float kn[13];
    kn[0] = kn[1] = kn[2] = kn[3] = -1.0f;
    float cum = 0.0f;
    #pragma unroll
    for (int k = 0; k < 5; k++) {
        cum += d[k] / dsum * 2.0f;
        kn[4 + k] = -1.0f + cum;
    }
    kn[9] = kn[10] = kn[11] = kn[12] = 1.0f;

    // Reciprocals of the 33 knot-difference denominators (masked to 0).
    for (int t = lane; t < 33; t += 32) {
        int dd, j;
        if (t < 12)      { dd = 1; j = t; }
        else if (t < 23) { dd = 2; j = t - 12; }
        else             { dd = 3; j = t - 23; }
        float den = kn[dd + j] - kn[j];
        s_rc[t] = (den > 1e-8f) ? 1.0f / den : 0.0f;
    }
    __syncthreads();

    // Lanes 0..23: each samples ONE node of ONE interval.
    if (lane < 24) {
        int j = lane >> 2, k = lane & 3;
        float lo = kn[3 + j], hi = kn[4 + j];
        float u = lo + (hi - lo) * (0.125f + 0.25f * (float)k);
        s_fv[lane] = eval_ref_spline(u, kn, s_rc, cf);
    } else if (s == 0) {
        int h = lane - 24;
        if (h < HID_) {
            float a0 = op_alpha[h * 2 + 0] + gumbel[h * 2 + 0];
            float a1 = op_alpha[h * 2 + 1] + gumbel[h * 2 + 1];
            float mx = fmaxf(a0, a1);
            float e0 = expf(a0 - mx), e1 = expf(a1 - mx);
            float inv = 1.0f / (e0 + e1);
            g_params[PARAMS_W + h * 2 + 0] = e0 * inv;
            g_params[PARAMS_W + h * 2 + 1] = e1 * inv;
        }
        if (lane == 28) g_params[PARAMS_B] = base_offset[0];
    }
    __syncthreads();

    float* P = g_params + s * SPL_STRIDE;
    if (lane < 5) P[lane] = kn[4 + lane];  // interior knots (float4 + scalar)

    // Lanes 0..5: fit exact cubic on interval j via fp32 divided differences.
    // Nodes are equispaced in normalized coord s=(x-m)/w at {-3/8,-1/8,1/8,3/8};
    // all denominators are multiples of w -> single reciprocal rw.
    if (lane < 6) {
        int j = lane;
        float lo = kn[3 + j], hi = kn[4 + j];
        float w = hi - lo;
        float m = lo + 0.5f * w;
        float rw = 1.0f / w;           // only division in the fit
        float f0 = s_fv[j * 4 + 0], f1 = s_fv[j * 4 + 1];
        float f2 = s_fv[j * 4 + 2], f3 = s_fv[j * 4 + 3];
        // Newton divided differences in s (spacing 1/4):
        float d1a = 4.0f * (f1 - f0);
        float d1b = 4.0f * (f2 - f1);
        float d1c = 4.0f * (f3 - f2);
        float d2a = 2.0f * (d1b - d1a);
        float d2b = 2.0f * (d1c - d1b);
        float d3  = (4.0f / 3.0f) * (d2b - d2a);
        // Expand Newton form to monomial in s:
        // p = ((d3*(s-s2)+d2a)*(s-s1)+d1a)*(s-s0)+f0 ; s0=-3/8, s1=-1/8, s2=1/8
        float p0 = d3, p1 = 0.0f, p2 = 0.0f, p3 = 0.0f;
        const float nodes[3] = {0.125f, -0.125f, -0.375f};
        const float adds[3]  = {d2a, d1a, f0};
        #pragma unroll
        for (int st = 0; st < 3; st++) {
            float vv = nodes[st];
            float q3 = p2, q2 = p1, q1 = p0;
            float q0 = adds[st] - vv * p0;
            q1 -= vv * p1; q2 -= vv * p2; q3 -= vv * p3;
            p0 = q0; p1 = q1; p2 = q2; p3 = q3;
        }
        // Convert s-monomial to t-monomial (t = x - m = w*s): c_k = p_k * rw^k
        float rw2 = rw * rw;
        P[8 + j] = m;
        P[16 + 4 * j + 0] = p0;
        P[16 + 4 * j + 1] = p1 * rw;
        P[16 + 4 * j + 2] = p2 * rw2;
        P[16 + 4 * j + 3] = p3 * rw2 * rw;
    }
}

__device__ __forceinline__ float eval_spline_sh(float x, const float* sp) {
    float4 kv = *reinterpret_cast<const float4*>(sp);   // broadcast LDS.128
    float k4 = sp[4];
    int idx = (x >= kv.x) + (x >= kv.y) + (x >= kv.z) + (x >= kv.w) + (x >= k4);
    float m = sp[8 + idx];
    float4 c = *reinterpret_cast<const float4*>(sp + 16 + 4 * idx);
    float t = x - m;
    return fmaf(fmaf(fmaf(c.w, t, c.z), t, c.y), t, c.x);
}

__global__ void __launch_bounds__(256) kan_main_kernel(const float4* __restrict__ x,
                                                       float* __restrict__ out, int n) {
    __shared__ __align__(16) float sp[832];
    for (int k = threadIdx.x; k < PARAMS_N; k += blockDim.x) sp[k] = g_params[k];
    __syncthreads();

    int i0 = blockIdx.x * blockDim.x + threadIdx.x;
    if (i0 >= n) return;

    float4 xv = x[i0];
    float xi[4] = {xv.x, xv.y, xv.z, xv.w};

    float acc = sp[PARAMS_B];
    #pragma unroll
    for (int h = 0; h < HID_; h++) {
        float sum = 0.0f, prod = 1.0f;
        #pragma unroll
        for (int i = 0; i < IN_; i++) {
            float v = eval_spline_sh(xi[i], sp + (h * IN_ + i) * SPL_STRIDE);
            sum += v;
            prod *= fminf(fmaxf(v, -5.0f), 5.0f);
        }
        float hid = sp[PARAMS_W + h * 2 + 0] * sum + sp[PARAMS_W + h * 2 + 1] * prod;
        float v2 = 0.0f;
        if (hid >= -1.0f && hid <= 1.0f)
            v2 = eval_spline_sh(hid, sp + (16 + h) * SPL_STRIDE);
        acc += v2;
    }
    out[i0] = acc;
}

extern "C" void kernel_launch(void* const* d_in, const int* in_sizes, int n_in,
                              void* d_out, int out_size) {
    const float* x          = (const float*)d_in[0];
    const float* l1_coeffs  = (const float*)d_in[1];
    const float* l1_kd      = (const float*)d_in[2];
    const float* op_alpha   = (const float*)d_in[3];
    const float* gumbel     = (const float*)d_in[4];
    const float* l2_coeffs  = (const float*)d_in[5];
    const float* l2_kd      = (const float*)d_in[6];
    const float* base_off   = (const float*)d_in[7];
    float* out = (float*)d_out;

    int n = in_sizes[0] / IN_;  // N samples

    kan_setup_kernel<<<NSPL, 32>>>(l1_coeffs, l1_kd, op_alpha, gumbel,
                                   l2_coeffs, l2_kd, base_off);
    int threads = 256;
    int blocks = (n + threads - 1) / threads;
    kan_main_kernel<<<blocks, threads>>>((const float4*)x, out, n);
}